// round 5
// baseline (speedup 1.0000x reference)
#include <cuda_runtime.h>

#define TT    2048
#define BB    32
#define FEATD 512
#define HIDD  512
#define NCOL4 2048
#define NCTA  128
#define NH    4
#define NC    16
#define NTHR  256
#define ROWSZ (BB*HIDD)      // 16384 floats per timestep of h

// smem layout (floats)
#define ZH_OFF   0            // z_h: [32][512]
#define BUFA_OFF 16384        // x chunk0: [32][256]
#define BUFB_OFF 24576        // x chunk1: [32][256]
#define W_OFF    32768        // W_s: 16384
#define G_OFF    49152        // gates: 32*17
#define SMEM_FLOATS (G_OFF + 32*17)

__device__ __align__(256) float g_hA[(TT+1)*ROWSZ];
__device__ __align__(256) float g_hB[(TT+1)*ROWSZ];
__device__ unsigned int g_count = 0;
__device__ unsigned int g_gen   = 0;

__device__ __forceinline__ void grid_barrier() {
    __threadfence();
    __syncthreads();
    if (threadIdx.x == 0) {
        volatile unsigned int* vgen = &g_gen;
        unsigned int gen = *vgen;
        if (atomicAdd(&g_count, 1u) == NCTA - 1u) {
            atomicExch(&g_count, 0u);
            __threadfence();
            atomicAdd(&g_gen, 1u);
        } else {
            while (*vgen == gen) {}
        }
    }
    __syncthreads();
}

// JAX silently downcasts int64->int32 unless x64 mode is on; detect at runtime.
__device__ __forceinline__ int load_length(const void* lp, int b) {
    const int* L = (const int*)lp;
    bool is64 = true;
    #pragma unroll
    for (int w = 1; w < 32; w += 2) is64 &= (L[w] == 0);
    return is64 ? (int)((const long long*)lp)[b] : L[b];
}

// packed dual-fp32 FMA (Blackwell f32x2), pair carried in a 64-bit int reg.
typedef unsigned long long u64t;
__device__ __forceinline__ u64t ffma2(u64t a, u64t b, u64t c) {
    u64t d;
    asm("fma.rn.f32x2 %0, %1, %2, %3;" : "=l"(d) : "l"(a), "l"(b), "l"(c));
    return d;
}
__device__ __forceinline__ float plo(u64t d){ return __uint_as_float((unsigned)d); }
__device__ __forceinline__ float phi(u64t d){ return __uint_as_float((unsigned)(d >> 32)); }

__device__ __forceinline__ void cpa16(unsigned int dst, const void* src) {
    asm volatile("cp.async.cg.shared.global [%0], [%1], 16;" :: "r"(dst), "l"(src));
}
#define CPA_COMMIT() asm volatile("cp.async.commit_group;")
#define CPA_WAIT(n)  asm volatile("cp.async.wait_group %0;" :: "n"(n))

__device__ __forceinline__ unsigned int smem_u32(const void* p) {
    unsigned int a;
    asm("{ .reg .u64 t; cvta.to.shared.u64 t, %1; cvt.u32.u64 %0, t; }" : "=r"(a) : "l"(p));
    return a;
}

__global__ void __launch_bounds__(NTHR, 1)
lstm_persistent(const float* __restrict__ x,
                const void* __restrict__ length,
                const float* __restrict__ Wih0, const float* __restrict__ Whh0,
                const float* __restrict__ b0v,
                const float* __restrict__ Wih1, const float* __restrict__ Whh1,
                const float* __restrict__ b1v)
{
    extern __shared__ float smem[];
    float* z_h     = smem + ZH_OFF;
    float* bufA    = smem + BUFA_OFF;
    float* bufB    = smem + BUFB_OFF;
    float* W_s     = smem + W_OFF;
    float* gates_s = smem + G_OFF;
    const unsigned int zh_u  = smem_u32(z_h);
    const unsigned int bA_u  = smem_u32(bufA);
    const unsigned int bB_u  = smem_u32(bufB);

    const int tid   = threadIdx.x;
    const int hbase = blockIdx.x * NH;

    const int c   = tid & 15;              // gate column (c = hh*4 + gate)
    const int bh  = (tid >> 4) & 1;
    const int bg  = (tid >> 5) & 3;
    const int kh  = tid >> 7;              // k-half within each chunk
    const int b0i = bg*8 + bh*4;           // 4 batch rows per thread

    const int eb  = tid & 31;              // elementwise mapping (tid<128)
    const int ehh = tid >> 5;
    int lb = 0;
    if (tid < 128) lb = load_length(length, eb);

    for (int layer = 0; layer < 2; ++layer) {
        const float* Wih  = layer ? Wih1 : Wih0;
        const float* Whh  = layer ? Whh1 : Whh0;
        const float* bias = layer ? b1v  : b0v;
        const float* xbase = layer ? (g_hA + ROWSZ) : x;
        float* hbuf = layer ? g_hB : g_hA;

        // drain any in-flight cp.async from previous layer before reusing buffers
        CPA_WAIT(0);
        __syncthreads();

        // Stage weights: W_s[(k>>2)*64 + c*4 + (k&3)] = W[k][col(c)]
        for (int i = tid; i < 1024*NC; i += NTHR) {
            int k  = i >> 4;
            int cc = i & 15;
            int col = ((cc & 3) << 9) + hbase + (cc >> 2);
            float w = (k < FEATD) ? Wih[(size_t)k*NCOL4 + col]
                                  : Whh[(size_t)(k-FEATD)*NCOL4 + col];
            W_s[((k >> 2) << 6) + (cc << 2) + (k & 3)] = w;
        }
        float bv = bias[((c & 3) << 9) + hbase + (c >> 2)];
        __syncthreads();

        // prime x chunk prefetch for t=0
        {
            const float* xrow = xbase;
            #pragma unroll
            for (int j = 0; j < 8; ++j) {
                int i = tid + j*NTHR;          // 0..2047
                int b = i >> 6, k4 = i & 63;
                cpa16(bA_u + ((b<<8) + (k4<<2))*4, xrow + b*512 + (k4<<2));
            }
            CPA_COMMIT();
            #pragma unroll
            for (int j = 0; j < 8; ++j) {
                int i = tid + j*NTHR;
                int b = i >> 6, k4 = i & 63;
                cpa16(bB_u + ((b<<8) + (k4<<2))*4, xrow + b*512 + 256 + (k4<<2));
            }
            CPA_COMMIT();
        }

        float creg = 0.f, hreg = 0.f;

        for (int t = 0; t < TT; ++t) {
            // issue h_t staging (async, awaited before h-GEMM)
            {
                const float* hrow = hbuf + (size_t)t*ROWSZ;
                #pragma unroll
                for (int j = 0; j < 16; ++j) {
                    int i = tid + j*NTHR;      // 0..4095
                    int b = i >> 7, k4 = i & 127;
                    cpa16(zh_u + ((b<<9) + (k4<<2))*4, hrow + b*512 + (k4<<2));
                }
                CPA_COMMIT();
            }

            u64t acc[8];
            #pragma unroll
            for (int j = 0; j < 8; ++j) acc[j] = 0ull;

            // ---- chunk A: k in [0,256), this thread kh*128..+128 ----
            CPA_WAIT(2);           // xc0(t) ready
            __syncthreads();
            {
                const float* wp = W_s + ((kh*128) >> 2)*64 + (c << 2);
                const float* zp = bufA + b0i*256 + kh*128;
                #pragma unroll 8
                for (int k4 = 0; k4 < 32; ++k4) {
                    ulonglong2 w  = *(const ulonglong2*)(wp + (k4 << 6));
                    ulonglong2 q0 = *(const ulonglong2*)(zp + (k4 << 2));
                    ulonglong2 q1 = *(const ulonglong2*)(zp + 256 + (k4 << 2));
                    ulonglong2 q2 = *(const ulonglong2*)(zp + 512 + (k4 << 2));
                    ulonglong2 q3 = *(const ulonglong2*)(zp + 768 + (k4 << 2));
                    acc[0]=ffma2(q0.x,w.x,acc[0]); acc[1]=ffma2(q0.y,w.y,acc[1]);
                    acc[2]=ffma2(q1.x,w.x,acc[2]); acc[3]=ffma2(q1.y,w.y,acc[3]);
                    acc[4]=ffma2(q2.x,w.x,acc[4]); acc[5]=ffma2(q2.y,w.y,acc[5]);
                    acc[6]=ffma2(q3.x,w.x,acc[6]); acc[7]=ffma2(q3.y,w.y,acc[7]);
                }
            }

            // ---- chunk B: k in [256,512) ----
            CPA_WAIT(1);           // xc1(t) ready
            __syncthreads();
            {
                const float* wp = W_s + ((256 + kh*128) >> 2)*64 + (c << 2);
                const float* zp = bufB + b0i*256 + kh*128;
                #pragma unroll 8
                for (int k4 = 0; k4 < 32; ++k4) {
                    ulonglong2 w  = *(const ulonglong2*)(wp + (k4 << 6));
                    ulonglong2 q0 = *(const ulonglong2*)(zp + (k4 << 2));
                    ulonglong2 q1 = *(const ulonglong2*)(zp + 256 + (k4 << 2));
                    ulonglong2 q2 = *(const ulonglong2*)(zp + 512 + (k4 << 2));
                    ulonglong2 q3 = *(const ulonglong2*)(zp + 768 + (k4 << 2));
                    acc[0]=ffma2(q0.x,w.x,acc[0]); acc[1]=ffma2(q0.y,w.y,acc[1]);
                    acc[2]=ffma2(q1.x,w.x,acc[2]); acc[3]=ffma2(q1.y,w.y,acc[3]);
                    acc[4]=ffma2(q2.x,w.x,acc[4]); acc[5]=ffma2(q2.y,w.y,acc[5]);
                    acc[6]=ffma2(q3.x,w.x,acc[6]); acc[7]=ffma2(q3.y,w.y,acc[7]);
                }
            }
            __syncthreads();       // all threads done reading bufA/bufB

            // prefetch next step's x chunks (full step to land)
            {
                int tn = (t + 1 < TT) ? (t + 1) : (TT - 1);
                const float* xrow = xbase + (size_t)tn*ROWSZ;
                #pragma unroll
                for (int j = 0; j < 8; ++j) {
                    int i = tid + j*NTHR;
                    int b = i >> 6, k4 = i & 63;
                    cpa16(bA_u + ((b<<8) + (k4<<2))*4, xrow + b*512 + (k4<<2));
                }
                CPA_COMMIT();
                #pragma unroll
                for (int j = 0; j < 8; ++j) {
                    int i = tid + j*NTHR;
                    int b = i >> 6, k4 = i & 63;
                    cpa16(bB_u + ((b<<8) + (k4<<2))*4, xrow + b*512 + 256 + (k4<<2));
                }
                CPA_COMMIT();
            }

            // ---- chunk H: k in [512,1024), this thread kh*256..+256 ----
            CPA_WAIT(2);           // h(t) ready (only xc0/xc1(t+1) remain)
            __syncthreads();
            {
                const float* wp = W_s + ((512 + kh*256) >> 2)*64 + (c << 2);
                const float* zp = z_h + b0i*512 + kh*256;
                #pragma unroll 8
                for (int k4 = 0; k4 < 64; ++k4) {
                    ulonglong2 w  = *(const ulonglong2*)(wp + (k4 << 6));
                    ulonglong2 q0 = *(const ulonglong2*)(zp + (k4 << 2));
                    ulonglong2 q1 = *(const ulonglong2*)(zp + 512 + (k4 << 2));
                    ulonglong2 q2 = *(const ulonglong2*)(zp + 1024 + (k4 << 2));
                    ulonglong2 q3 = *(const ulonglong2*)(zp + 1536 + (k4 << 2));
                    acc[0]=ffma2(q0.x,w.x,acc[0]); acc[1]=ffma2(q0.y,w.y,acc[1]);
                    acc[2]=ffma2(q1.x,w.x,acc[2]); acc[3]=ffma2(q1.y,w.y,acc[3]);
                    acc[4]=ffma2(q2.x,w.x,acc[4]); acc[5]=ffma2(q2.y,w.y,acc[5]);
                    acc[6]=ffma2(q3.x,w.x,acc[6]); acc[7]=ffma2(q3.y,w.y,acc[7]);
                }
            }

            // ---- reduce: per-b scalar sums, then cross-kh via smem ----
            float a0 = plo(acc[0])+phi(acc[0])+plo(acc[1])+phi(acc[1]);
            float a1 = plo(acc[2])+phi(acc[2])+plo(acc[3])+phi(acc[3]);
            float a2 = plo(acc[4])+phi(acc[4])+plo(acc[5])+phi(acc[5]);
            float a3 = plo(acc[6])+phi(acc[6])+plo(acc[7])+phi(acc[7]);

            if (kh == 1) {
                gates_s[(b0i+0)*17 + c] = a0;
                gates_s[(b0i+1)*17 + c] = a1;
                gates_s[(b0i+2)*17 + c] = a2;
                gates_s[(b0i+3)*17 + c] = a3;
            }
            __syncthreads();
            if (kh == 0) {
                gates_s[(b0i+0)*17 + c] += a0 + bv;
                gates_s[(b0i+1)*17 + c] += a1 + bv;
                gates_s[(b0i+2)*17 + c] += a2 + bv;
                gates_s[(b0i+3)*17 + c] += a3 + bv;
            }
            __syncthreads();

            // ---- LSTM elementwise ----
            if (tid < 128) {
                float fg = gates_s[eb*17 + ehh*4 + 0];
                float ig = gates_s[eb*17 + ehh*4 + 1];
                float og = gates_s[eb*17 + ehh*4 + 2];
                float gg = gates_s[eb*17 + ehh*4 + 3];
                float cn, hn;
                if (t < lb) {
                    float sf = 1.f/(1.f + __expf(-fg));
                    float si = 1.f/(1.f + __expf(-ig));
                    float so = 1.f/(1.f + __expf(-og));
                    float tg = 2.f/(1.f + __expf(-2.f*gg)) - 1.f;
                    cn = sf*creg + si*tg;
                    float tc = 2.f/(1.f + __expf(-2.f*cn)) - 1.f;
                    hn = so*tc;
                } else {
                    cn = creg;
                    hn = hreg;
                }
                creg = cn;
                hreg = hn;
                hbuf[(size_t)(t+1)*ROWSZ + eb*HIDD + hbase + ehh] = hn;
            }
            grid_barrier();
        }
    }
}

// out[r][a] = h1[r] . Wfc[:,a] + bfc[a],  h1 row = g_hB row r+32
__global__ void __launch_bounds__(256)
fc_kernel(const float* __restrict__ Wfc, const float* __restrict__ bfc,
          float* __restrict__ out)
{
    __shared__ float w_s[128*64];
    __shared__ float h_s[32*128];
    const int tid = threadIdx.x;
    const int rbase = blockIdx.x * 32;
    const int a  = tid & 63;
    const int r4 = tid >> 6;

    float acc[8];
    float bvv = bfc[a];
    #pragma unroll
    for (int j = 0; j < 8; ++j) acc[j] = bvv;

    for (int kc = 0; kc < 512; kc += 128) {
        __syncthreads();
        for (int i = tid; i < 128*64/4; i += 256)
            ((float4*)w_s)[i] = ((const float4*)(Wfc + (size_t)kc*64))[i];
        for (int i = tid; i < 32*128/4; i += 256) {
            int r  = i >> 5;
            int k4 = i & 31;
            ((float4*)(h_s + r*128))[k4] =
                *(const float4*)(g_hB + (size_t)(rbase + r + BB)*HIDD + kc + (k4 << 2));
        }
        __syncthreads();
        #pragma unroll 4
        for (int k = 0; k < 128; ++k) {
            float w = w_s[(k << 6) + a];
            #pragma unroll
            for (int j = 0; j < 8; ++j)
                acc[j] += h_s[(r4 + 4*j)*128 + k] * w;
        }
    }
    #pragma unroll
    for (int j = 0; j < 8; ++j)
        out[(size_t)(rbase + r4 + 4*j)*64 + a] = acc[j];
}

extern "C" void kernel_launch(void* const* d_in, const int* in_sizes, int n_in,
                              void* d_out, int out_size)
{
    const float* x      = (const float*)d_in[0];
    const void*  length = (const void*)d_in[1];
    const float* Wih0   = (const float*)d_in[2];
    const float* Whh0   = (const float*)d_in[3];
    const float* b0v    = (const float*)d_in[4];
    const float* Wih1   = (const float*)d_in[5];
    const float* Whh1   = (const float*)d_in[6];
    const float* b1v    = (const float*)d_in[7];
    const float* Wfc    = (const float*)d_in[8];
    const float* bfc    = (const float*)d_in[9];
    float* out = (float*)d_out;

    const int smem_bytes = SMEM_FLOATS * (int)sizeof(float); // ~194 KB
    cudaFuncSetAttribute(lstm_persistent,
                         cudaFuncAttributeMaxDynamicSharedMemorySize, smem_bytes);

    lstm_persistent<<<NCTA, NTHR, smem_bytes>>>(x, length, Wih0, Whh0, b0v,
                                                Wih1, Whh1, b1v);
    fc_kernel<<<(TT*BB)/32, 256>>>(Wfc, bfc, out);
}

// round 6
// speedup vs baseline: 1.4945x; 1.4945x over previous
#include <cuda_runtime.h>

#define TT    2048
#define BB    32
#define FEATD 512
#define HIDD  512
#define NCOL4 2048
#define NCTA  128
#define NH    4
#define NC    16
#define NTHR  256
#define ROWSZ (BB*HIDD)      // 16384 floats per timestep of h

// smem layout (floats)
#define ZX_OFF   0            // z_x: [32][512]
#define ZH_OFF   16384        // z_h: [32][512]
#define W_OFF    32768        // W_s: 16384
#define G_OFF    49152        // gates: 32*17
#define SMEM_FLOATS (G_OFF + 32*17)   // 49696 floats ~ 194 KB

__device__ __align__(256) float g_hA[(TT+1)*ROWSZ];
__device__ __align__(256) float g_hB[(TT+1)*ROWSZ];
__device__ unsigned int g_count = 0;
__device__ unsigned int g_gen   = 0;

__device__ __forceinline__ void grid_barrier() {
    __threadfence();
    __syncthreads();
    if (threadIdx.x == 0) {
        volatile unsigned int* vgen = &g_gen;
        unsigned int gen = *vgen;
        if (atomicAdd(&g_count, 1u) == NCTA - 1u) {
            atomicExch(&g_count, 0u);
            __threadfence();
            atomicAdd(&g_gen, 1u);
        } else {
            while (*vgen == gen) {}
        }
    }
    __syncthreads();
}

// JAX silently downcasts int64->int32 unless x64 mode is on; detect at runtime.
__device__ __forceinline__ int load_length(const void* lp, int b) {
    const int* L = (const int*)lp;
    bool is64 = true;
    #pragma unroll
    for (int w = 1; w < 32; w += 2) is64 &= (L[w] == 0);
    return is64 ? (int)((const long long*)lp)[b] : L[b];
}

__device__ __forceinline__ void cpa16(unsigned int dst, const void* src) {
    asm volatile("cp.async.cg.shared.global [%0], [%1], 16;" :: "r"(dst), "l"(src));
}
#define CPA_COMMIT() asm volatile("cp.async.commit_group;")
#define CPA_WAIT0()  asm volatile("cp.async.wait_group 0;")

__device__ __forceinline__ unsigned int smem_u32(const void* p) {
    unsigned int a;
    asm("{ .reg .u64 t; cvta.to.shared.u64 t, %1; cvt.u32.u64 %0, t; }" : "=r"(a) : "l"(p));
    return a;
}

__global__ void __launch_bounds__(NTHR, 1)
lstm_persistent(const float* __restrict__ x,
                const void* __restrict__ length,
                const float* __restrict__ Wih0, const float* __restrict__ Whh0,
                const float* __restrict__ b0v,
                const float* __restrict__ Wih1, const float* __restrict__ Whh1,
                const float* __restrict__ b1v)
{
    extern __shared__ float smem[];
    float* z_x     = smem + ZX_OFF;
    float* z_h     = smem + ZH_OFF;
    float* W_s     = smem + W_OFF;
    float* gates_s = smem + G_OFF;
    const unsigned int zx_u = smem_u32(z_x);
    const unsigned int zh_u = smem_u32(z_h);

    const int tid   = threadIdx.x;
    const int hbase = blockIdx.x * NH;

    const int c   = tid & 15;              // gate column (c = hh*4 + gate)
    const int bh  = (tid >> 4) & 1;
    const int bg  = (tid >> 5) & 3;
    const int kh  = tid >> 7;              // k-half within each 512-K block
    const int b0i = bg*8 + bh*4;           // 4 batch rows per thread

    const int eb  = tid & 31;              // elementwise mapping (tid<128)
    const int ehh = tid >> 5;
    int lb = 0;
    if (tid < 128) lb = load_length(length, eb);

    for (int layer = 0; layer < 2; ++layer) {
        const float* Wih  = layer ? Wih1 : Wih0;
        const float* Whh  = layer ? Whh1 : Whh0;
        const float* bias = layer ? b1v  : b0v;
        const float* xbase = layer ? (g_hA + ROWSZ) : x;
        float* hbuf = layer ? g_hB : g_hA;

        // Stage weights: W_s[(k>>2)*64 + c*4 + (k&3)] = W[k][col(c)]
        __syncthreads();
        for (int i = tid; i < 1024*NC; i += NTHR) {
            int k  = i >> 4;
            int cc = i & 15;
            int col = ((cc & 3) << 9) + hbase + (cc >> 2);
            float w = (k < FEATD) ? Wih[(size_t)k*NCOL4 + col]
                                  : Whh[(size_t)(k-FEATD)*NCOL4 + col];
            W_s[((k >> 2) << 6) + (cc << 2) + (k & 3)] = w;
        }
        float bv = bias[((c & 3) << 9) + hbase + (c >> 2)];

        // load x(0) into z_x
        {
            const float* xrow = xbase;
            #pragma unroll
            for (int j = 0; j < 16; ++j) {
                int i = tid + j*NTHR;
                int b = i >> 7, k4 = i & 127;
                cpa16(zx_u + ((b << 9) + (k4 << 2))*4, xrow + b*512 + (k4 << 2));
            }
            CPA_COMMIT();
        }
        CPA_WAIT0();
        __syncthreads();

        float creg = 0.f, hreg = 0.f;

        for (int t = 0; t < TT; ++t) {
            // 1) stage h(t) asynchronously; awaited after the x-GEMM
            {
                const float* hrow = hbuf + (size_t)t*ROWSZ;
                #pragma unroll
                for (int j = 0; j < 16; ++j) {
                    int i = tid + j*NTHR;
                    int b = i >> 7, k4 = i & 127;
                    cpa16(zh_u + ((b << 9) + (k4 << 2))*4, hrow + b*512 + (k4 << 2));
                }
                CPA_COMMIT();
            }

            // 2) prefetch x(t+1) into registers (latency hidden by x-GEMM)
            float4 xp[16];
            {
                int tn = (t + 1 < TT) ? (t + 1) : (TT - 1);
                const float4* xnext = (const float4*)(xbase + (size_t)tn*ROWSZ);
                #pragma unroll
                for (int j = 0; j < 16; ++j)
                    xp[j] = __ldcg(xnext + tid + j*NTHR);
            }

            float a0 = 0.f, a1 = 0.f, a2 = 0.f, a3 = 0.f;

            // 3) x-GEMM: k in [0,512), this thread kh*256..+256
            {
                const float* wp = W_s + ((kh*256) >> 2)*64 + (c << 2);
                const float* zp = z_x + b0i*512 + kh*256;
                #pragma unroll 8
                for (int k4 = 0; k4 < 64; ++k4) {
                    float4 w  = *(const float4*)(wp + (k4 << 6));
                    float4 z0 = *(const float4*)(zp + (k4 << 2));
                    float4 z1 = *(const float4*)(zp + 512  + (k4 << 2));
                    float4 z2 = *(const float4*)(zp + 1024 + (k4 << 2));
                    float4 z3 = *(const float4*)(zp + 1536 + (k4 << 2));
                    a0 += z0.x*w.x; a0 += z0.y*w.y; a0 += z0.z*w.z; a0 += z0.w*w.w;
                    a1 += z1.x*w.x; a1 += z1.y*w.y; a1 += z1.z*w.z; a1 += z1.w*w.w;
                    a2 += z2.x*w.x; a2 += z2.y*w.y; a2 += z2.z*w.z; a2 += z2.w*w.w;
                    a3 += z3.x*w.x; a3 += z3.y*w.y; a3 += z3.z*w.z; a3 += z3.w*w.w;
                }
            }

            // 4) h(t) must be resident; also closes all z_x reads of step t
            CPA_WAIT0();
            __syncthreads();

            // 5) store x(t+1) to z_x (all step-t reads completed at the sync)
            #pragma unroll
            for (int j = 0; j < 16; ++j) {
                int i = tid + j*NTHR;
                int b = i >> 7, k4 = i & 127;
                *(float4*)(z_x + (b << 9) + (k4 << 2)) = xp[j];
            }

            // 6) h-GEMM: k in [512,1024)
            {
                const float* wp = W_s + ((512 + kh*256) >> 2)*64 + (c << 2);
                const float* zp = z_h + b0i*512 + kh*256;
                #pragma unroll 8
                for (int k4 = 0; k4 < 64; ++k4) {
                    float4 w  = *(const float4*)(wp + (k4 << 6));
                    float4 z0 = *(const float4*)(zp + (k4 << 2));
                    float4 z1 = *(const float4*)(zp + 512  + (k4 << 2));
                    float4 z2 = *(const float4*)(zp + 1024 + (k4 << 2));
                    float4 z3 = *(const float4*)(zp + 1536 + (k4 << 2));
                    a0 += z0.x*w.x; a0 += z0.y*w.y; a0 += z0.z*w.z; a0 += z0.w*w.w;
                    a1 += z1.x*w.x; a1 += z1.y*w.y; a1 += z1.z*w.z; a1 += z1.w*w.w;
                    a2 += z2.x*w.x; a2 += z2.y*w.y; a2 += z2.z*w.z; a2 += z2.w*w.w;
                    a3 += z3.x*w.x; a3 += z3.y*w.y; a3 += z3.z*w.z; a3 += z3.w*w.w;
                }
            }

            // 7) cross-kh reduce via smem
            if (kh == 1) {
                gates_s[(b0i+0)*17 + c] = a0;
                gates_s[(b0i+1)*17 + c] = a1;
                gates_s[(b0i+2)*17 + c] = a2;
                gates_s[(b0i+3)*17 + c] = a3;
            }
            __syncthreads();
            if (kh == 0) {
                gates_s[(b0i+0)*17 + c] += a0 + bv;
                gates_s[(b0i+1)*17 + c] += a1 + bv;
                gates_s[(b0i+2)*17 + c] += a2 + bv;
                gates_s[(b0i+3)*17 + c] += a3 + bv;
            }
            __syncthreads();

            // 8) LSTM elementwise: thread owns (b, hidden) state
            if (tid < 128) {
                float fg = gates_s[eb*17 + ehh*4 + 0];
                float ig = gates_s[eb*17 + ehh*4 + 1];
                float og = gates_s[eb*17 + ehh*4 + 2];
                float gg = gates_s[eb*17 + ehh*4 + 3];
                float cn, hn;
                if (t < lb) {
                    float sf = 1.f/(1.f + __expf(-fg));
                    float si = 1.f/(1.f + __expf(-ig));
                    float so = 1.f/(1.f + __expf(-og));
                    float tg = 2.f/(1.f + __expf(-2.f*gg)) - 1.f;
                    cn = sf*creg + si*tg;
                    float tc = 2.f/(1.f + __expf(-2.f*cn)) - 1.f;
                    hn = so*tc;
                } else {
                    cn = creg;
                    hn = hreg;
                }
                creg = cn;
                hreg = hn;
                hbuf[(size_t)(t+1)*ROWSZ + eb*HIDD + hbase + ehh] = hn;
            }
            grid_barrier();
        }
    }
}

// out[r][a] = h1[r] . Wfc[:,a] + bfc[a],  h1 row = g_hB row r+32
__global__ void __launch_bounds__(256)
fc_kernel(const float* __restrict__ Wfc, const float* __restrict__ bfc,
          float* __restrict__ out)
{
    __shared__ float w_s[128*64];
    __shared__ float h_s[32*128];
    const int tid = threadIdx.x;
    const int rbase = blockIdx.x * 32;
    const int a  = tid & 63;
    const int r4 = tid >> 6;

    float acc[8];
    float bvv = bfc[a];
    #pragma unroll
    for (int j = 0; j < 8; ++j) acc[j] = bvv;

    for (int kc = 0; kc < 512; kc += 128) {
        __syncthreads();
        for (int i = tid; i < 128*64/4; i += 256)
            ((float4*)w_s)[i] = ((const float4*)(Wfc + (size_t)kc*64))[i];
        for (int i = tid; i < 32*128/4; i += 256) {
            int r  = i >> 5;
            int k4 = i & 31;
            ((float4*)(h_s + r*128))[k4] =
                *(const float4*)(g_hB + (size_t)(rbase + r + BB)*HIDD + kc + (k4 << 2));
        }
        __syncthreads();
        #pragma unroll 4
        for (int k = 0; k < 128; ++k) {
            float w = w_s[(k << 6) + a];
            #pragma unroll
            for (int j = 0; j < 8; ++j)
                acc[j] += h_s[(r4 + 4*j)*128 + k] * w;
        }
    }
    #pragma unroll
    for (int j = 0; j < 8; ++j)
        out[(size_t)(rbase + r4 + 4*j)*64 + a] = acc[j];
}

extern "C" void kernel_launch(void* const* d_in, const int* in_sizes, int n_in,
                              void* d_out, int out_size)
{
    const float* x      = (const float*)d_in[0];
    const void*  length = (const void*)d_in[1];
    const float* Wih0   = (const float*)d_in[2];
    const float* Whh0   = (const float*)d_in[3];
    const float* b0v    = (const float*)d_in[4];
    const float* Wih1   = (const float*)d_in[5];
    const float* Whh1   = (const float*)d_in[6];
    const float* b1v    = (const float*)d_in[7];
    const float* Wfc    = (const float*)d_in[8];
    const float* bfc    = (const float*)d_in[9];
    float* out = (float*)d_out;

    const int smem_bytes = SMEM_FLOATS * (int)sizeof(float); // ~194 KB
    cudaFuncSetAttribute(lstm_persistent,
                         cudaFuncAttributeMaxDynamicSharedMemorySize, smem_bytes);

    lstm_persistent<<<NCTA, NTHR, smem_bytes>>>(x, length, Wih0, Whh0, b0v,
                                                Wih1, Whh1, b1v);
    fc_kernel<<<(TT*BB)/32, 256>>>(Wfc, bfc, out);
}